// round 13
// baseline (speedup 1.0000x reference)
#include <cuda_runtime.h>
#include <cuda_bf16.h>
#include <mma.h>
#include <cstdint>

using namespace nvcuda;

#define BB 8
#define NN 2048
#define FIN 128
#define ODIM 256
#define NROWS (BB*NN)
#define LD 144          // bf16 leading dim: 288 B/row -> every row 32B-aligned
#define DLD 260         // f32 epilogue stride

// scratch (static device arrays — no allocation)
__device__ __align__(16) float g_w[8 * FIN];          // wsrc[4][128], wdst[4][128]
__device__ __align__(16) float g_r[NROWS * 4];        // exp(-0.8*src)
__device__ __align__(16) float g_ed[NROWS * 8];       // exp(dst)[4], exp(0.2*dst)[4]
__device__ __align__(16) float g_num[NROWS * 4];      // max(ed, r*eq)
__device__ __align__(16) float g_acc[NROWS * 4];      // scan denominators
__device__ __align__(16) __nv_bfloat16 g_Wh[ODIM * FIN];  // bf16 hi(W)
__device__ __align__(16) __nv_bfloat16 g_Wl[ODIM * FIN];  // bf16 lo(W)

// ---------------------------------------------------------------------------
// Kernel 0: W -> bf16 hi/lo (separate arrays, row-major [256][128])
// ---------------------------------------------------------------------------
__global__ __launch_bounds__(256) void wprep_kernel(const float* __restrict__ W) {
    int idx = blockIdx.x * 256 + threadIdx.x;    // 0..32767
    float x = W[idx];
    __nv_bfloat16 h = __float2bfloat16_rn(x);
    __nv_bfloat16 l = __float2bfloat16_rn(x - __bfloat162float(h));
    g_Wh[idx] = h;
    g_Wl[idx] = l;
}

// ---------------------------------------------------------------------------
// Kernel 1: head-projection vectors  w[s][h][k] = sum_d a[h][d] * W[h*64+d][k]
// ---------------------------------------------------------------------------
__global__ __launch_bounds__(256) void vec_kernel(const float* __restrict__ W,
                                                  const float* __restrict__ asrc,
                                                  const float* __restrict__ adst) {
    const int h = blockIdx.x >> 1, s = blockIdx.x & 1;
    const float* av = s ? adst : asrc;
    const int tid = threadIdx.x;
    const int g = tid >> 7;
    const int k = tid & 127;
    float acc = 0.f;
#pragma unroll 8
    for (int dd = 0; dd < 32; dd++) {
        int d = g * 32 + dd;
        acc = fmaf(av[h * 64 + d], W[(size_t)(h * 64 + d) * FIN + k], acc);
    }
    __shared__ float red[256];
    red[tid] = acc;
    __syncthreads();
    if (g == 0)
        g_w[(s * 4 + h) * FIN + k] = red[k] + red[128 + k];
}

// ---------------------------------------------------------------------------
// Kernel 2: per-row src/dst from X + exp tables + numerator
// ---------------------------------------------------------------------------
__global__ __launch_bounds__(256) void row_kernel(const float* __restrict__ X) {
    __shared__ float sw[8 * FIN];
    const int tid = threadIdx.x;
    ((float4*)sw)[tid] = ((const float4*)g_w)[tid];
    __syncthreads();

    const int l = tid & 31, w = tid >> 5;
    const int row = blockIdx.x * 8 + w;
    float4 x4 = ((const float4*)(X + (size_t)row * FIN))[l];
    float dot[8];
#pragma unroll
    for (int v = 0; v < 8; v++) {
        float4 w4 = ((const float4*)(sw + v * FIN))[l];
        dot[v] = x4.x * w4.x + x4.y * w4.y + x4.z * w4.z + x4.w * w4.w;
    }
#pragma unroll
    for (int off = 16; off; off >>= 1)
#pragma unroll
        for (int v = 0; v < 8; v++)
            dot[v] += __shfl_xor_sync(0xffffffffu, dot[v], off);

    if (l == 0) {
#pragma unroll
        for (int h = 0; h < 4; h++) {
            float src = dot[h], dst = dot[4 + h];
            float r  = expf(-0.8f * src);
            float ed = expf(dst);
            float eq = expf(0.2f * dst);
            g_r[row * 4 + h]      = r;
            g_ed[row * 8 + h]     = ed;
            g_ed[row * 8 + 4 + h] = eq;
            g_num[row * 4 + h]    = fmaxf(ed, r * eq);
        }
    }
}

// ---------------------------------------------------------------------------
// Kernel 3: masked scan  acc_ih = sum_j A_ij * max(ed_jh, r_ih*eq_jh)
// ---------------------------------------------------------------------------
#define SCAN_SMEM (NN * 8 * 4)   // 64 KB

__global__ __launch_bounds__(256, 2) void scan_kernel(const float* __restrict__ A) {
    extern __shared__ float sm[];
    float4* sed = (float4*)sm;
    float4* seq = (float4*)(sm + NN * 4);
    const int tid = threadIdx.x;
    const int b = blockIdx.y;
    const int l = tid & 31;
    const int r0 = blockIdx.x * 32 + (tid >> 5) * 4;

    {
        const float4* ge = (const float4*)(g_ed + (size_t)b * NN * 8);
        for (int t = tid; t < NN; t += 256) {
            sed[t] = ge[2 * t];
            seq[t] = ge[2 * t + 1];
        }
    }
    __syncthreads();

    float rr[4][4];
#pragma unroll
    for (int ii = 0; ii < 4; ii++) {
        float4 rv = *(const float4*)&g_r[(size_t)(b * NN + r0 + ii) * 4];
        rr[ii][0] = rv.x; rr[ii][1] = rv.y; rr[ii][2] = rv.z; rr[ii][3] = rv.w;
    }

    const float* Ar[4];
#pragma unroll
    for (int ii = 0; ii < 4; ii++)
        Ar[ii] = A + ((size_t)b * NN + (r0 + ii)) * NN;

    float acc[4][4];
#pragma unroll
    for (int ii = 0; ii < 4; ii++)
#pragma unroll
        for (int h = 0; h < 4; h++) acc[ii][h] = 0.f;

    float cur[4][4], nxt[4][4];
#pragma unroll
    for (int s = 0; s < 4; s++)
#pragma unroll
        for (int ii = 0; ii < 4; ii++)
            cur[s][ii] = __ldcs(&Ar[ii][l + 32 * s]);

    for (int rnd = 0; rnd < 16; rnd++) {
        const int jb = (rnd < 15) ? (rnd + 1) * 128 + l : rnd * 128 + l;
#pragma unroll
        for (int s = 0; s < 4; s++)
#pragma unroll
            for (int ii = 0; ii < 4; ii++)
                nxt[s][ii] = __ldcs(&Ar[ii][jb + 32 * s]);

#pragma unroll
        for (int s = 0; s < 4; s++) {
            const int j = rnd * 128 + s * 32 + l;
            float4 ed = sed[j];
            float4 eq = seq[j];
#pragma unroll
            for (int ii = 0; ii < 4; ii++) {
                const float a = cur[s][ii];
                acc[ii][0] = fmaf(a, fmaxf(ed.x, rr[ii][0] * eq.x), acc[ii][0]);
                acc[ii][1] = fmaf(a, fmaxf(ed.y, rr[ii][1] * eq.y), acc[ii][1]);
                acc[ii][2] = fmaf(a, fmaxf(ed.z, rr[ii][2] * eq.z), acc[ii][2]);
                acc[ii][3] = fmaf(a, fmaxf(ed.w, rr[ii][3] * eq.w), acc[ii][3]);
            }
        }
#pragma unroll
        for (int s = 0; s < 4; s++)
#pragma unroll
            for (int ii = 0; ii < 4; ii++) cur[s][ii] = nxt[s][ii];
    }

#pragma unroll
    for (int off = 16; off; off >>= 1)
#pragma unroll
        for (int ii = 0; ii < 4; ii++)
#pragma unroll
            for (int h = 0; h < 4; h++)
                acc[ii][h] += __shfl_xor_sync(0xffffffffu, acc[ii][h], off);

    if (l == 0) {
#pragma unroll
        for (int ii = 0; ii < 4; ii++) {
            float* gp = g_acc + (size_t)(b * NN + r0 + ii) * 4;
#pragma unroll
            for (int h = 0; h < 4; h++) gp[h] = acc[ii][h];
        }
    }
}

// ---------------------------------------------------------------------------
// Kernel 4: wmma bf16 GEMM, 3-pass hi/lo split:
//   acc = Xh@Wh^T; acc += Xh@Wl^T; acc += Xl@Wh^T   (fp32 accum)
// CTA: 128 rows x 256 cols, 512 thr (16 warps 4x4), warp tile 32x64.
// smem: Xh,Xl [128][144] + Wh,Wl [256][144] bf16 = 221,184 B (1 CTA/SM).
// Fused diag epilogue via smem D.
// ---------------------------------------------------------------------------
#define SM_XH 0
#define SM_XL (128 * LD * 2)                       // 36,864
#define SM_WH (SM_XL + 128 * LD * 2)               // 73,728
#define SM_WL (SM_WH + 256 * LD * 2)               // 147,456
#define TCG_SMEM (SM_WL + 256 * LD * 2)            // 221,184

__global__ __launch_bounds__(512) void tc_gemm_kernel(const float* __restrict__ X,
                                                      float* __restrict__ out) {
    extern __shared__ char smc[];
    __nv_bfloat16* Xh = (__nv_bfloat16*)(smc + SM_XH);   // [128][LD]
    __nv_bfloat16* Xl = (__nv_bfloat16*)(smc + SM_XL);
    __nv_bfloat16* Wh = (__nv_bfloat16*)(smc + SM_WH);   // [256][LD]
    __nv_bfloat16* Wl = (__nv_bfloat16*)(smc + SM_WL);
    const int tid = threadIdx.x;
    const int m0 = blockIdx.x * 128;

    // load Wh/Wl: 256 rows x 256 B each (16 uint4/row)
    {
        const uint4* sh = (const uint4*)g_Wh;
        const uint4* sl = (const uint4*)g_Wl;
#pragma unroll
        for (int it = 0; it < 8; it++) {
            int u = tid + it * 512;              // 0..4095
            int row = u >> 4, c = u & 15;
            *(uint4*)((char*)(Wh + row * LD) + c * 16) = sh[row * 16 + c];
            *(uint4*)((char*)(Wl + row * LD) + c * 16) = sl[row * 16 + c];
        }
    }
    // load + split X: thread -> row tid>>2, 32-float chunk q=tid&3
    {
        const int row = tid >> 2, q = tid & 3;
        const float4* xr = (const float4*)(X + (size_t)(m0 + row) * FIN + q * 32);
        __nv_bfloat16* xh = Xh + row * LD + q * 32;
        __nv_bfloat16* xl = Xl + row * LD + q * 32;
#pragma unroll
        for (int g = 0; g < 4; g++) {
            float4 v0 = xr[2 * g], v1 = xr[2 * g + 1];
            float f[8] = {v0.x, v0.y, v0.z, v0.w, v1.x, v1.y, v1.z, v1.w};
            unsigned hp[4], lp[4];
#pragma unroll
            for (int p = 0; p < 4; p++) {
                __nv_bfloat16 h0 = __float2bfloat16_rn(f[2 * p]);
                __nv_bfloat16 h1 = __float2bfloat16_rn(f[2 * p + 1]);
                __nv_bfloat16 l0 = __float2bfloat16_rn(f[2 * p] - __bfloat162float(h0));
                __nv_bfloat16 l1 = __float2bfloat16_rn(f[2 * p + 1] - __bfloat162float(h1));
                hp[p] = ((unsigned)__bfloat16_as_ushort(h1) << 16) | __bfloat16_as_ushort(h0);
                lp[p] = ((unsigned)__bfloat16_as_ushort(l1) << 16) | __bfloat16_as_ushort(l0);
            }
            *(uint4*)(xh + g * 8) = make_uint4(hp[0], hp[1], hp[2], hp[3]);
            *(uint4*)(xl + g * 8) = make_uint4(lp[0], lp[1], lp[2], lp[3]);
        }
    }
    __syncthreads();

    const int wid = tid >> 5;
    const int wm = wid & 3, wn = wid >> 2;     // rows wm*32, cols wn*64

    wmma::fragment<wmma::accumulator, 16, 16, 16, float> acc[2][4];
#pragma unroll
    for (int i = 0; i < 2; i++)
#pragma unroll
        for (int j = 0; j < 4; j++) wmma::fill_fragment(acc[i][j], 0.f);

    const __nv_bfloat16* Ap[3] = {Xh, Xh, Xl};
    const __nv_bfloat16* Bp[3] = {Wh, Wl, Wh};
#pragma unroll
    for (int p = 0; p < 3; p++) {
        const __nv_bfloat16* Am = Ap[p];
        const __nv_bfloat16* Bm = Bp[p];
#pragma unroll
        for (int ks = 0; ks < 8; ks++) {
            const int k0 = ks * 16;
            wmma::fragment<wmma::matrix_a, 16, 16, 16, __nv_bfloat16, wmma::row_major> af[2];
            wmma::fragment<wmma::matrix_b, 16, 16, 16, __nv_bfloat16, wmma::col_major> bf[4];
#pragma unroll
            for (int i = 0; i < 2; i++)
                wmma::load_matrix_sync(af[i], Am + (wm * 32 + i * 16) * LD + k0, LD);
#pragma unroll
            for (int j = 0; j < 4; j++)
                wmma::load_matrix_sync(bf[j], Bm + (wn * 64 + j * 16) * LD + k0, LD);
#pragma unroll
            for (int i = 0; i < 2; i++)
#pragma unroll
                for (int j = 0; j < 4; j++)
                    wmma::mma_sync(acc[i][j], af[i], bf[j], acc[i][j]);
        }
    }
    __syncthreads();   // all operand reads done before smem reuse

    // store accumulators to smem D [128][DLD]
    float* Ds = (float*)smc;
#pragma unroll
    for (int i = 0; i < 2; i++)
#pragma unroll
        for (int j = 0; j < 4; j++)
            wmma::store_matrix_sync(Ds + (wm * 32 + i * 16) * DLD + wn * 64 + j * 16,
                                    acc[i][j], DLD, wmma::mem_row_major);
    __syncthreads();

    // epilogue: row = tid>>2, 64-col chunk = tid&3 (chunk == head)
    {
        const int row = tid >> 2, ch = tid & 3;
        const size_t grow = (size_t)(m0 + row);
        float diag = __fdividef(g_num[grow * 4 + ch], g_acc[grow * 4 + ch]);
        const float4* dp = (const float4*)(Ds + row * DLD + ch * 64);
        float4* op = (float4*)(out + grow * ODIM + ch * 64);
#pragma unroll
        for (int q = 0; q < 16; q++) {
            float4 v = dp[q];
            op[q] = make_float4(v.x * diag, v.y * diag, v.z * diag, v.w * diag);
        }
    }
}

// ---------------------------------------------------------------------------
extern "C" void kernel_launch(void* const* d_in, const int* in_sizes, int n_in,
                              void* d_out, int out_size) {
    const float* A    = (const float*)d_in[0];
    const float* X    = (const float*)d_in[1];
    const float* W    = (const float*)d_in[2];
    const float* asrc = (const float*)d_in[3];
    const float* adst = (const float*)d_in[4];
    float* out = (float*)d_out;

    cudaFuncSetAttribute(scan_kernel, cudaFuncAttributeMaxDynamicSharedMemorySize,
                         SCAN_SMEM);
    cudaFuncSetAttribute(tc_gemm_kernel, cudaFuncAttributeMaxDynamicSharedMemorySize,
                         TCG_SMEM);

    wprep_kernel<<<128, 256>>>(W);
    vec_kernel<<<8, 256>>>(W, asrc, adst);
    row_kernel<<<NROWS / 8, 256>>>(X);
    scan_kernel<<<dim3(NN / 32, BB), 256, SCAN_SMEM>>>(A);
    tc_gemm_kernel<<<NROWS / 128, 512, TCG_SMEM>>>(X, out);
}

// round 15
// speedup vs baseline: 1.4292x; 1.4292x over previous
#include <cuda_runtime.h>
#include <cuda_bf16.h>
#include <mma.h>
#include <cstdint>

using namespace nvcuda;

#define BB 8
#define NN 2048
#define FIN 128
#define ODIM 256
#define NROWS (BB*NN)
#define LD 136          // bf16 leading dim: 272 B/row, 16B-aligned, LDSM conflict-free
#define DLD 260         // f32 epilogue stride

// scratch (static device arrays — no allocation)
__device__ __align__(16) float g_w[8 * FIN];          // wsrc[4][128], wdst[4][128]
__device__ __align__(16) float g_r[NROWS * 4];        // exp(-0.8*src)
__device__ __align__(16) float g_ed[NROWS * 8];       // exp(dst)[4], exp(0.2*dst)[4]
__device__ __align__(16) float g_num[NROWS * 4];      // max(ed, r*eq)
__device__ __align__(16) float g_acc[NROWS * 4];      // scan denominators
__device__ __align__(16) __nv_bfloat16 g_Wh[ODIM * FIN];  // bf16 hi(W)
__device__ __align__(16) __nv_bfloat16 g_Wl[ODIM * FIN];  // bf16 lo(W)

// ---------------------------------------------------------------------------
// Kernel 0: W -> bf16 hi/lo (separate arrays, row-major [256][128])
// ---------------------------------------------------------------------------
__global__ __launch_bounds__(256) void wprep_kernel(const float* __restrict__ W) {
    int idx = blockIdx.x * 256 + threadIdx.x;    // 0..32767
    float x = W[idx];
    __nv_bfloat16 h = __float2bfloat16_rn(x);
    __nv_bfloat16 l = __float2bfloat16_rn(x - __bfloat162float(h));
    g_Wh[idx] = h;
    g_Wl[idx] = l;
}

// ---------------------------------------------------------------------------
// Kernel 1: head-projection vectors  w[s][h][k] = sum_d a[h][d] * W[h*64+d][k]
// ---------------------------------------------------------------------------
__global__ __launch_bounds__(256) void vec_kernel(const float* __restrict__ W,
                                                  const float* __restrict__ asrc,
                                                  const float* __restrict__ adst) {
    const int h = blockIdx.x >> 1, s = blockIdx.x & 1;
    const float* av = s ? adst : asrc;
    const int tid = threadIdx.x;
    const int g = tid >> 7;
    const int k = tid & 127;
    float acc = 0.f;
#pragma unroll 8
    for (int dd = 0; dd < 32; dd++) {
        int d = g * 32 + dd;
        acc = fmaf(av[h * 64 + d], W[(size_t)(h * 64 + d) * FIN + k], acc);
    }
    __shared__ float red[256];
    red[tid] = acc;
    __syncthreads();
    if (g == 0)
        g_w[(s * 4 + h) * FIN + k] = red[k] + red[128 + k];
}

// ---------------------------------------------------------------------------
// Kernel 2: per-row src/dst from X + exp tables + numerator
// ---------------------------------------------------------------------------
__global__ __launch_bounds__(256) void row_kernel(const float* __restrict__ X) {
    __shared__ float sw[8 * FIN];
    const int tid = threadIdx.x;
    ((float4*)sw)[tid] = ((const float4*)g_w)[tid];
    __syncthreads();

    const int l = tid & 31, w = tid >> 5;
    const int row = blockIdx.x * 8 + w;
    float4 x4 = ((const float4*)(X + (size_t)row * FIN))[l];
    float dot[8];
#pragma unroll
    for (int v = 0; v < 8; v++) {
        float4 w4 = ((const float4*)(sw + v * FIN))[l];
        dot[v] = x4.x * w4.x + x4.y * w4.y + x4.z * w4.z + x4.w * w4.w;
    }
#pragma unroll
    for (int off = 16; off; off >>= 1)
#pragma unroll
        for (int v = 0; v < 8; v++)
            dot[v] += __shfl_xor_sync(0xffffffffu, dot[v], off);

    if (l == 0) {
#pragma unroll
        for (int h = 0; h < 4; h++) {
            float src = dot[h], dst = dot[4 + h];
            float r  = expf(-0.8f * src);
            float ed = expf(dst);
            float eq = expf(0.2f * dst);
            g_r[row * 4 + h]      = r;
            g_ed[row * 8 + h]     = ed;
            g_ed[row * 8 + 4 + h] = eq;
            g_num[row * 4 + h]    = fmaxf(ed, r * eq);
        }
    }
}

// ---------------------------------------------------------------------------
// Kernel 3: masked scan  acc_ih = sum_j A_ij * max(ed_jh, r_ih*eq_jh)
// Round-parity double buffering: no cur<-nxt register copies.
// ---------------------------------------------------------------------------
#define SCAN_SMEM (NN * 8 * 4)   // 64 KB

__global__ __launch_bounds__(256, 2) void scan_kernel(const float* __restrict__ A) {
    extern __shared__ float sm[];
    float4* sed = (float4*)sm;
    float4* seq = (float4*)(sm + NN * 4);
    const int tid = threadIdx.x;
    const int b = blockIdx.y;
    const int l = tid & 31;
    const int r0 = blockIdx.x * 32 + (tid >> 5) * 4;

    {
        const float4* ge = (const float4*)(g_ed + (size_t)b * NN * 8);
        for (int t = tid; t < NN; t += 256) {
            sed[t] = ge[2 * t];
            seq[t] = ge[2 * t + 1];
        }
    }
    __syncthreads();

    float rr[4][4];
#pragma unroll
    for (int ii = 0; ii < 4; ii++) {
        float4 rv = *(const float4*)&g_r[(size_t)(b * NN + r0 + ii) * 4];
        rr[ii][0] = rv.x; rr[ii][1] = rv.y; rr[ii][2] = rv.z; rr[ii][3] = rv.w;
    }

    const float* Ar[4];
#pragma unroll
    for (int ii = 0; ii < 4; ii++)
        Ar[ii] = A + ((size_t)b * NN + (r0 + ii)) * NN;

    float acc[4][4];
#pragma unroll
    for (int ii = 0; ii < 4; ii++)
#pragma unroll
        for (int h = 0; h < 4; h++) acc[ii][h] = 0.f;

    float bufA[4][4], bufB[4][4];          // [stage][row]
#pragma unroll
    for (int s = 0; s < 4; s++)
#pragma unroll
        for (int ii = 0; ii < 4; ii++)
            bufA[s][ii] = __ldcs(&Ar[ii][l + 32 * s]);

    // macro: prefetch round RB into BUF (clamped), then process round RP from PBUF
#define SCAN_HALF(PBUF, RP, BUF, RB)                                          \
    {                                                                         \
        const int jb = ((RB) <= 15 ? (RB) : (RP)) * 128 + l;                  \
        _Pragma("unroll")                                                     \
        for (int s = 0; s < 4; s++)                                           \
            _Pragma("unroll")                                                 \
            for (int ii = 0; ii < 4; ii++)                                    \
                BUF[s][ii] = __ldcs(&Ar[ii][jb + 32 * s]);                    \
        _Pragma("unroll")                                                     \
        for (int s = 0; s < 4; s++) {                                         \
            const int j = (RP) * 128 + s * 32 + l;                            \
            float4 ed = sed[j];                                               \
            float4 eq = seq[j];                                               \
            _Pragma("unroll")                                                 \
            for (int ii = 0; ii < 4; ii++) {                                  \
                const float a = PBUF[s][ii];                                  \
                acc[ii][0] = fmaf(a, fmaxf(ed.x, rr[ii][0] * eq.x), acc[ii][0]); \
                acc[ii][1] = fmaf(a, fmaxf(ed.y, rr[ii][1] * eq.y), acc[ii][1]); \
                acc[ii][2] = fmaf(a, fmaxf(ed.z, rr[ii][2] * eq.z), acc[ii][2]); \
                acc[ii][3] = fmaf(a, fmaxf(ed.w, rr[ii][3] * eq.w), acc[ii][3]); \
            }                                                                 \
        }                                                                     \
    }

    for (int rnd = 0; rnd < 16; rnd += 2) {
        SCAN_HALF(bufA, rnd,     bufB, rnd + 1)
        SCAN_HALF(bufB, rnd + 1, bufA, rnd + 2)
    }
#undef SCAN_HALF

#pragma unroll
    for (int off = 16; off; off >>= 1)
#pragma unroll
        for (int ii = 0; ii < 4; ii++)
#pragma unroll
            for (int h = 0; h < 4; h++)
                acc[ii][h] += __shfl_xor_sync(0xffffffffu, acc[ii][h], off);

    if (l == 0) {
#pragma unroll
        for (int ii = 0; ii < 4; ii++) {
            float* gp = g_acc + (size_t)(b * NN + r0 + ii) * 4;
#pragma unroll
            for (int h = 0; h < 4; h++) gp[h] = acc[ii][h];
        }
    }
}

// ---------------------------------------------------------------------------
// Kernel 4: wmma bf16 GEMM, 3-pass hi/lo split (acc = XhWh + XhWl + XlWh).
// CTA: 128 rows x 256 cols, 512 thr (16 warps 4x4), warp tile 32x64.
// B fragment loaded inside the j-loop (register pressure < 128, no spills).
// LD=136 -> LDSM conflict-free. Fused diag epilogue via smem D.
// ---------------------------------------------------------------------------
#define SM_XH 0
#define SM_XL (128 * LD * 2)                       // 34,816
#define SM_WH (SM_XL + 128 * LD * 2)               // 69,632
#define SM_WL (SM_WH + 256 * LD * 2)               // 139,264
#define TCG_SMEM (SM_WL + 256 * LD * 2)            // 208,896

__global__ __launch_bounds__(512) void tc_gemm_kernel(const float* __restrict__ X,
                                                      float* __restrict__ out) {
    extern __shared__ char smc[];
    __nv_bfloat16* Xh = (__nv_bfloat16*)(smc + SM_XH);   // [128][LD]
    __nv_bfloat16* Xl = (__nv_bfloat16*)(smc + SM_XL);
    __nv_bfloat16* Wh = (__nv_bfloat16*)(smc + SM_WH);   // [256][LD]
    __nv_bfloat16* Wl = (__nv_bfloat16*)(smc + SM_WL);
    const int tid = threadIdx.x;
    const int m0 = blockIdx.x * 128;

    // load Wh/Wl: 256 rows x 256 B each (16 uint4/row)
    {
        const uint4* sh = (const uint4*)g_Wh;
        const uint4* sl = (const uint4*)g_Wl;
#pragma unroll
        for (int it = 0; it < 8; it++) {
            int u = tid + it * 512;              // 0..4095
            int row = u >> 4, c = u & 15;
            *(uint4*)((char*)(Wh + row * LD) + c * 16) = sh[row * 16 + c];
            *(uint4*)((char*)(Wl + row * LD) + c * 16) = sl[row * 16 + c];
        }
    }
    // load + split X: thread -> row tid>>2, 32-float chunk q=tid&3
    {
        const int row = tid >> 2, q = tid & 3;
        const float4* xr = (const float4*)(X + (size_t)(m0 + row) * FIN + q * 32);
        __nv_bfloat16* xh = Xh + row * LD + q * 32;
        __nv_bfloat16* xl = Xl + row * LD + q * 32;
#pragma unroll
        for (int g = 0; g < 4; g++) {
            float4 v0 = xr[2 * g], v1 = xr[2 * g + 1];
            float f[8] = {v0.x, v0.y, v0.z, v0.w, v1.x, v1.y, v1.z, v1.w};
            unsigned hp[4], lp[4];
#pragma unroll
            for (int p = 0; p < 4; p++) {
                __nv_bfloat16 h0 = __float2bfloat16_rn(f[2 * p]);
                __nv_bfloat16 h1 = __float2bfloat16_rn(f[2 * p + 1]);
                __nv_bfloat16 l0 = __float2bfloat16_rn(f[2 * p] - __bfloat162float(h0));
                __nv_bfloat16 l1 = __float2bfloat16_rn(f[2 * p + 1] - __bfloat162float(h1));
                hp[p] = ((unsigned)__bfloat16_as_ushort(h1) << 16) | __bfloat16_as_ushort(h0);
                lp[p] = ((unsigned)__bfloat16_as_ushort(l1) << 16) | __bfloat16_as_ushort(l0);
            }
            *(uint4*)(xh + g * 8) = make_uint4(hp[0], hp[1], hp[2], hp[3]);
            *(uint4*)(xl + g * 8) = make_uint4(lp[0], lp[1], lp[2], lp[3]);
        }
    }
    __syncthreads();

    const int wid = tid >> 5;
    const int wm = wid & 3, wn = wid >> 2;     // rows wm*32, cols wn*64

    wmma::fragment<wmma::accumulator, 16, 16, 16, float> acc[2][4];
#pragma unroll
    for (int i = 0; i < 2; i++)
#pragma unroll
        for (int j = 0; j < 4; j++) wmma::fill_fragment(acc[i][j], 0.f);

    const __nv_bfloat16* Ap[3] = {Xh, Xh, Xl};
    const __nv_bfloat16* Bp[3] = {Wh, Wl, Wh};
#pragma unroll
    for (int p = 0; p < 3; p++) {
        const __nv_bfloat16* Am = Ap[p];
        const __nv_bfloat16* Bm = Bp[p];
#pragma unroll
        for (int ks = 0; ks < 8; ks++) {
            const int k0 = ks * 16;
            wmma::fragment<wmma::matrix_a, 16, 16, 16, __nv_bfloat16, wmma::row_major> af[2];
            wmma::load_matrix_sync(af[0], Am + (wm * 32) * LD + k0, LD);
            wmma::load_matrix_sync(af[1], Am + (wm * 32 + 16) * LD + k0, LD);
#pragma unroll
            for (int j = 0; j < 4; j++) {
                wmma::fragment<wmma::matrix_b, 16, 16, 16, __nv_bfloat16, wmma::col_major> bf;
                wmma::load_matrix_sync(bf, Bm + (wn * 64 + j * 16) * LD + k0, LD);
                wmma::mma_sync(acc[0][j], af[0], bf, acc[0][j]);
                wmma::mma_sync(acc[1][j], af[1], bf, acc[1][j]);
            }
        }
    }
    __syncthreads();   // all operand reads done before smem reuse

    // store accumulators to smem D [128][DLD]
    float* Ds = (float*)smc;
#pragma unroll
    for (int i = 0; i < 2; i++)
#pragma unroll
        for (int j = 0; j < 4; j++)
            wmma::store_matrix_sync(Ds + (wm * 32 + i * 16) * DLD + wn * 64 + j * 16,
                                    acc[i][j], DLD, wmma::mem_row_major);
    __syncthreads();

    // epilogue: row = tid>>2, 64-col chunk = tid&3 (chunk == head)
    {
        const int row = tid >> 2, ch = tid & 3;
        const size_t grow = (size_t)(m0 + row);
        float diag = __fdividef(g_num[grow * 4 + ch], g_acc[grow * 4 + ch]);
        const float4* dp = (const float4*)(Ds + row * DLD + ch * 64);
        float4* op = (float4*)(out + grow * ODIM + ch * 64);
#pragma unroll
        for (int q = 0; q < 16; q++) {
            float4 v = dp[q];
            op[q] = make_float4(v.x * diag, v.y * diag, v.z * diag, v.w * diag);
        }
    }
}

// ---------------------------------------------------------------------------
extern "C" void kernel_launch(void* const* d_in, const int* in_sizes, int n_in,
                              void* d_out, int out_size) {
    const float* A    = (const float*)d_in[0];
    const float* X    = (const float*)d_in[1];
    const float* W    = (const float*)d_in[2];
    const float* asrc = (const float*)d_in[3];
    const float* adst = (const float*)d_in[4];
    float* out = (float*)d_out;

    cudaFuncSetAttribute(scan_kernel, cudaFuncAttributeMaxDynamicSharedMemorySize,
                         SCAN_SMEM);
    cudaFuncSetAttribute(tc_gemm_kernel, cudaFuncAttributeMaxDynamicSharedMemorySize,
                         TCG_SMEM);

    wprep_kernel<<<128, 256>>>(W);
    vec_kernel<<<8, 256>>>(W, asrc, adst);
    row_kernel<<<NROWS / 8, 256>>>(X);
    scan_kernel<<<dim3(NN / 32, BB), 256, SCAN_SMEM>>>(A);
    tc_gemm_kernel<<<NROWS / 128, 512, TCG_SMEM>>>(X, out);
}

// round 17
// speedup vs baseline: 1.7785x; 1.2445x over previous
#include <cuda_runtime.h>
#include <cstdint>

#define BB 8
#define NN 2048
#define FIN 128
#define ODIM 256
#define NROWS (BB*NN)

// scratch (static device arrays — no allocation)
__device__ __align__(16) float g_T[NROWS * ODIM];   // X @ W^T (16 MB)
__device__ __align__(16) float g_w[8 * FIN];        // wsrc[4][128], wdst[4][128]
__device__ __align__(16) float g_r[NROWS * 4];      // exp(-0.8*src)
__device__ __align__(16) float g_ed[NROWS * 8];     // exp(dst)[4], exp(0.2*dst)[4]
__device__ __align__(16) float g_num[NROWS * 4];    // max(ed, r*eq)
__device__ __align__(16) float g_acc[NROWS * 4];    // scan denominators

// ---------------------------------------------------------------------------
// Kernel 1: head-projection vectors  w[s][h][k] = sum_d a[h][d] * W[h*64+d][k]
// ---------------------------------------------------------------------------
__global__ __launch_bounds__(256) void vec_kernel(const float* __restrict__ W,
                                                  const float* __restrict__ asrc,
                                                  const float* __restrict__ adst) {
    const int h = blockIdx.x >> 1, s = blockIdx.x & 1;
    const float* av = s ? adst : asrc;
    const int tid = threadIdx.x;
    const int g = tid >> 7;
    const int k = tid & 127;
    float acc = 0.f;
#pragma unroll 8
    for (int dd = 0; dd < 32; dd++) {
        int d = g * 32 + dd;
        acc = fmaf(av[h * 64 + d], W[(size_t)(h * 64 + d) * FIN + k], acc);
    }
    __shared__ float red[256];
    red[tid] = acc;
    __syncthreads();
    if (g == 0)
        g_w[(s * 4 + h) * FIN + k] = red[k] + red[128 + k];
}

// ---------------------------------------------------------------------------
// Kernel 2: per-row src/dst from X + exp tables + numerator
// ---------------------------------------------------------------------------
__global__ __launch_bounds__(256) void row_kernel(const float* __restrict__ X) {
    __shared__ float sw[8 * FIN];
    const int tid = threadIdx.x;
    ((float4*)sw)[tid] = ((const float4*)g_w)[tid];
    __syncthreads();

    const int l = tid & 31, w = tid >> 5;
    const int row = blockIdx.x * 8 + w;
    float4 x4 = ((const float4*)(X + (size_t)row * FIN))[l];
    float dot[8];
#pragma unroll
    for (int v = 0; v < 8; v++) {
        float4 w4 = ((const float4*)(sw + v * FIN))[l];
        dot[v] = x4.x * w4.x + x4.y * w4.y + x4.z * w4.z + x4.w * w4.w;
    }
#pragma unroll
    for (int off = 16; off; off >>= 1)
#pragma unroll
        for (int v = 0; v < 8; v++)
            dot[v] += __shfl_xor_sync(0xffffffffu, dot[v], off);

    if (l == 0) {
#pragma unroll
        for (int h = 0; h < 4; h++) {
            float src = dot[h], dst = dot[4 + h];
            float r  = expf(-0.8f * src);
            float ed = expf(dst);
            float eq = expf(0.2f * dst);
            g_r[row * 4 + h]      = r;
            g_ed[row * 8 + h]     = ed;
            g_ed[row * 8 + 4 + h] = eq;
            g_num[row * 4 + h]    = fmaxf(ed, r * eq);
        }
    }
}

// ---------------------------------------------------------------------------
// Kernel 3: FUSED role-split kernel, grid 296 @ occ 2.
//   bid <  148: SCAN role  — units u in [bid*512/148, (bid+1)*512/148)
//               unit u: batch b=u>>6, rowgroup u&63 (32 rows)
//   bid >= 148: GEMM role  — units for gid=bid-148; unit u: m0=(u>>2)*128,
//               c0=(u&3)*64; writes raw T tile.
// Wave-1 placement puts bids c and c+148 on the same SM -> 1 scan + 1 gemm
// per SM; the DRAM-bound scan fills the fma-bound gemm's issue gaps.
// ---------------------------------------------------------------------------
#define XS 132
#define WCS 132
#define FUSED_SMEM ((128*XS + 64*WCS) * 4)   // 101,376 B -> 2 blocks/SM

__global__ __launch_bounds__(256, 2) void fused_kernel(const float* __restrict__ A,
                                                       const float* __restrict__ X,
                                                       const float* __restrict__ W) {
    extern __shared__ float sm[];
    const int tid = threadIdx.x;
    const int bid = blockIdx.x;

    if (bid < 148) {
        // ============================ SCAN role ============================
        float4* sed = (float4*)sm;             // exp(dst) [NN]
        float4* seq = (float4*)(sm + NN * 4);  // exp(0.2*dst) [NN]
        const int l = tid & 31;
        const int u0 = (bid * 512) / 148;
        const int u1 = ((bid + 1) * 512) / 148;
        int prevb = -1;

        for (int u = u0; u < u1; u++) {
            const int b = u >> 6;
            if (b != prevb) {
                __syncthreads();               // previous unit done with tables
                const float4* ge = (const float4*)(g_ed + (size_t)b * NN * 8);
                for (int t = tid; t < NN; t += 256) {
                    sed[t] = ge[2 * t];
                    seq[t] = ge[2 * t + 1];
                }
                __syncthreads();
                prevb = b;
            }
            const int r0 = (u & 63) * 32 + (tid >> 5) * 4;

            float rr[4][4];
#pragma unroll
            for (int ii = 0; ii < 4; ii++) {
                float4 rv = *(const float4*)&g_r[(size_t)(b * NN + r0 + ii) * 4];
                rr[ii][0] = rv.x; rr[ii][1] = rv.y; rr[ii][2] = rv.z; rr[ii][3] = rv.w;
            }
            const float* Ar[4];
#pragma unroll
            for (int ii = 0; ii < 4; ii++)
                Ar[ii] = A + ((size_t)b * NN + (r0 + ii)) * NN;

            float acc[4][4];
#pragma unroll
            for (int ii = 0; ii < 4; ii++)
#pragma unroll
                for (int h = 0; h < 4; h++) acc[ii][h] = 0.f;

            float bufA[4][4], bufB[4][4];      // [stage][row]
#pragma unroll
            for (int s = 0; s < 4; s++)
#pragma unroll
                for (int ii = 0; ii < 4; ii++)
                    bufA[s][ii] = __ldcs(&Ar[ii][l + 32 * s]);

#define SCAN_HALF(PBUF, RP, BUF, RB)                                          \
    {                                                                         \
        const int jb = ((RB) <= 15 ? (RB) : (RP)) * 128 + l;                  \
        _Pragma("unroll")                                                     \
        for (int s = 0; s < 4; s++)                                           \
            _Pragma("unroll")                                                 \
            for (int ii = 0; ii < 4; ii++)                                    \
                BUF[s][ii] = __ldcs(&Ar[ii][jb + 32 * s]);                    \
        _Pragma("unroll")                                                     \
        for (int s = 0; s < 4; s++) {                                         \
            const int j = (RP) * 128 + s * 32 + l;                            \
            float4 ed = sed[j];                                               \
            float4 eq = seq[j];                                               \
            _Pragma("unroll")                                                 \
            for (int ii = 0; ii < 4; ii++) {                                  \
                const float a = PBUF[s][ii];                                  \
                acc[ii][0] = fmaf(a, fmaxf(ed.x, rr[ii][0] * eq.x), acc[ii][0]); \
                acc[ii][1] = fmaf(a, fmaxf(ed.y, rr[ii][1] * eq.y), acc[ii][1]); \
                acc[ii][2] = fmaf(a, fmaxf(ed.z, rr[ii][2] * eq.z), acc[ii][2]); \
                acc[ii][3] = fmaf(a, fmaxf(ed.w, rr[ii][3] * eq.w), acc[ii][3]); \
            }                                                                 \
        }                                                                     \
    }
            for (int rnd = 0; rnd < 16; rnd += 2) {
                SCAN_HALF(bufA, rnd,     bufB, rnd + 1)
                SCAN_HALF(bufB, rnd + 1, bufA, rnd + 2)
            }
#undef SCAN_HALF

#pragma unroll
            for (int off = 16; off; off >>= 1)
#pragma unroll
                for (int ii = 0; ii < 4; ii++)
#pragma unroll
                    for (int h = 0; h < 4; h++)
                        acc[ii][h] += __shfl_xor_sync(0xffffffffu, acc[ii][h], off);

            if (l == 0) {
#pragma unroll
                for (int ii = 0; ii < 4; ii++) {
                    float* gp = g_acc + (size_t)(b * NN + r0 + ii) * 4;
#pragma unroll
                    for (int h = 0; h < 4; h++) gp[h] = acc[ii][h];
                }
            }
        }
    } else {
        // ============================ GEMM role ============================
        float* Xs = sm;               // [m][k], stride XS
        float* Ws = sm + 128 * XS;    // [c][k], stride WCS
        const int gid = bid - 148;
        const int u0 = (gid * 512) / 148;
        const int u1 = ((gid + 1) * 512) / 148;
        bool first = true;

        for (int u = u0; u < u1; u++) {
            const int m0 = (u >> 2) * 128;
            const int c0 = (u & 3) * 64;
            if (!first) __syncthreads();   // previous unit done reading tiles
            first = false;
#pragma unroll
            for (int it = 0; it < 16; it++) {
                int g = tid + it * 256;
                int r = g >> 5, kq = g & 31;
                float4 v = ((const float4*)(X + (size_t)(m0 + r) * FIN))[kq];
                *(float4*)&Xs[r * XS + 4 * kq] = v;
            }
#pragma unroll
            for (int it = 0; it < 8; it++) {
                int g = tid + it * 256;
                int c = g >> 5, kq = g & 31;
                float4 v = ((const float4*)(W + (size_t)(c0 + c) * FIN))[kq];
                *(float4*)&Ws[c * WCS + 4 * kq] = v;
            }
            __syncthreads();

            const int tx = tid & 15, ty = tid >> 4;
            const int r0 = ty * 8;

            unsigned long long acc[8][4];
#pragma unroll
            for (int i = 0; i < 8; i++)
#pragma unroll
                for (int j = 0; j < 4; j++) acc[i][j] = 0ull;

#pragma unroll 2
            for (int k0 = 0; k0 < 128; k0 += 4) {
                ulonglong2 bv[4];
#pragma unroll
                for (int j = 0; j < 4; j++)
                    bv[j] = *(const ulonglong2*)&Ws[(tx + 16 * j) * WCS + k0];
#pragma unroll
                for (int i = 0; i < 8; i++) {
                    ulonglong2 av = *(const ulonglong2*)&Xs[(r0 + i) * XS + k0];
#pragma unroll
                    for (int j = 0; j < 4; j++) {
                        asm("fma.rn.f32x2 %0, %1, %2, %0;"
                            : "+l"(acc[i][j]) : "l"(av.x), "l"(bv[j].x));
                        asm("fma.rn.f32x2 %0, %1, %2, %0;"
                            : "+l"(acc[i][j]) : "l"(av.y), "l"(bv[j].y));
                    }
                }
            }

#pragma unroll
            for (int i = 0; i < 8; i++) {
                float* Tr = g_T + (size_t)(m0 + r0 + i) * ODIM + c0;
#pragma unroll
                for (int j = 0; j < 4; j++) {
                    float lo, hi;
                    asm("mov.b64 {%0, %1}, %2;" : "=f"(lo), "=f"(hi) : "l"(acc[i][j]));
                    Tr[tx + 16 * j] = lo + hi;
                }
            }
        }
    }
}

// ---------------------------------------------------------------------------
// Kernel 4: out = (num/acc) * T   (4 rows per block)
// ---------------------------------------------------------------------------
__global__ __launch_bounds__(256) void scale_kernel(float* __restrict__ out) {
    const int tid = threadIdx.x;
    const int r = tid >> 6;
    const int f = tid & 63;
    const size_t row = (size_t)blockIdx.x * 4 + r;
    const int h = f >> 4;
    float diag = __fdividef(g_num[row * 4 + h], g_acc[row * 4 + h]);
    float4 t = ((const float4*)(g_T + row * ODIM))[f];
    ((float4*)(out + row * ODIM))[f] =
        make_float4(t.x * diag, t.y * diag, t.z * diag, t.w * diag);
}

// ---------------------------------------------------------------------------
extern "C" void kernel_launch(void* const* d_in, const int* in_sizes, int n_in,
                              void* d_out, int out_size) {
    const float* A    = (const float*)d_in[0];
    const float* X    = (const float*)d_in[1];
    const float* W    = (const float*)d_in[2];
    const float* asrc = (const float*)d_in[3];
    const float* adst = (const float*)d_in[4];
    float* out = (float*)d_out;

    cudaFuncSetAttribute(fused_kernel, cudaFuncAttributeMaxDynamicSharedMemorySize,
                         FUSED_SMEM);

    vec_kernel<<<8, 256>>>(W, asrc, adst);
    row_kernel<<<NROWS / 8, 256>>>(X);
    fused_kernel<<<296, 256, FUSED_SMEM>>>(A, X, W);
    scale_kernel<<<NROWS / 4, 256>>>(out);
}